// round 15
// baseline (speedup 1.0000x reference)
#include <cuda_runtime.h>
#include <cuda_fp16.h>
#include <cstdint>

#define B_ 2
#define L_ 512
#define V_ 64
#define D_ 128
#define NC_ 8
#define NR_MAX 96

// ---- static device scratch (no allocations allowed) ----
__device__ float  g_sumK[B_ * L_ * D_];
__device__ __half g_sKh[B_ * L_ * D_];
__device__ __half g_sKl[B_ * L_ * D_];
__device__ int    g_idx[B_][NC_][L_];
__device__ int    g_cnt[B_][NC_];

#define SCALE_ 0.08838834764831845f

__device__ __forceinline__ uint32_t packh2(float a, float b2) {
    __half2 h = __halves2half2(__float2half_rn(a), __float2half_rn(b2));
    return *reinterpret_cast<uint32_t*>(&h);
}

// ===========================================================================
// Prep kernel: blocks [0,1024) sumK (+fp16 hi/lo); [1024,1040) idx lists
// ===========================================================================
__global__ void prep_kernel(const float4* __restrict__ key4,
                            const int* __restrict__ label) {
    __shared__ float4 part[256];
    const int blk = blockIdx.x;

    if (blk < 1024) {
        int bl = blk;
        int g = threadIdx.x & 31, qd = threadIdx.x >> 5;
        const float4* p = key4 + (size_t)bl * (V_ * D_ / 4)
                        + (size_t)(qd * 8) * (D_ / 4) + g;
        float4 s = make_float4(0.f, 0.f, 0.f, 0.f);
#pragma unroll
        for (int vv = 0; vv < 8; vv++) {
            float4 t = p[(size_t)vv * (D_ / 4)];
            s.x += t.x; s.y += t.y; s.z += t.z; s.w += t.w;
        }
        part[threadIdx.x] = s;
        __syncthreads();
        if (qd < 4) {
            float4 a = part[threadIdx.x], b2 = part[threadIdx.x + 128];
            part[threadIdx.x] =
                make_float4(a.x + b2.x, a.y + b2.y, a.z + b2.z, a.w + b2.w);
        }
        __syncthreads();
        if (qd == 0) {
            float4 a = part[g], b2 = part[32 + g], c2 = part[64 + g], d2 = part[96 + g];
            float4 r = make_float4(a.x + b2.x + c2.x + d2.x, a.y + b2.y + c2.y + d2.y,
                                   a.z + b2.z + c2.z + d2.z, a.w + b2.w + c2.w + d2.w);
            ((float4*)g_sumK)[(size_t)bl * 32 + g] = r;
            __half hx = __float2half_rn(r.x), hy = __float2half_rn(r.y);
            __half hz = __float2half_rn(r.z), hw = __float2half_rn(r.w);
            size_t o = (size_t)bl * 64 + g * 2;
            { __half2 t = __halves2half2(hx, hy); ((uint32_t*)g_sKh)[o] = *(uint32_t*)&t; }
            { __half2 t = __halves2half2(hz, hw); ((uint32_t*)g_sKh)[o + 1] = *(uint32_t*)&t; }
            ((uint32_t*)g_sKl)[o] =
                packh2(r.x - __half2float(hx), r.y - __half2float(hy));
            ((uint32_t*)g_sKl)[o + 1] =
                packh2(r.z - __half2float(hz), r.w - __half2float(hw));
        }
    } else {
        if (threadIdx.x >= 32) return;
        int bc = blk - 1024;
        int c = bc & 7, b = bc >> 3;
        int lane = threadIdx.x;
        int cnt = 0;
        for (int l0 = 0; l0 < L_; l0 += 32) {
            int l = l0 + lane;
            int lbl = label[b * L_ + l];
            unsigned m = __ballot_sync(0xffffffffu, lbl == c);
            if (lbl == c) {
                int pos = cnt + __popc(m & ((1u << lane) - 1u));
                g_idx[b][c][pos] = l;
            }
            cnt += __popc(m);
        }
        if (lane == 0) g_cnt[b][c] = cnt;
    }
}

// ===========================================================================
// PTX helpers (family-common, valid on target sm_103)
// ===========================================================================
__device__ __forceinline__ uint32_t smem_u32(const void* p) {
    uint32_t a;
    asm("{ .reg .u64 t; cvta.to.shared.u64 t, %1; cvt.u32.u64 %0, t; }"
        : "=r"(a) : "l"(p));
    return a;
}
__device__ __forceinline__ void cpa16(uint32_t dst, const void* src) {
    asm volatile("cp.async.cg.shared.global [%0], [%1], 16;"
                 :: "r"(dst), "l"(src));
}
__device__ __forceinline__ void ldsm4(uint32_t addr, uint32_t* r) {
    asm volatile("ldmatrix.sync.aligned.m8n8.x4.shared.b16 {%0,%1,%2,%3}, [%4];"
                 : "=r"(r[0]), "=r"(r[1]), "=r"(r[2]), "=r"(r[3]) : "r"(addr));
}
__device__ __forceinline__ void ldsm4t(uint32_t addr, uint32_t* r) {
    asm volatile("ldmatrix.sync.aligned.m8n8.x4.trans.shared.b16 {%0,%1,%2,%3}, [%4];"
                 : "=r"(r[0]), "=r"(r[1]), "=r"(r[2]), "=r"(r[3]) : "r"(addr));
}
__device__ __forceinline__ void mma16816(float* c, const uint32_t* a,
                                         uint32_t b0, uint32_t b1) {
    asm volatile(
        "mma.sync.aligned.m16n8k16.row.col.f32.f16.f16.f32 "
        "{%0,%1,%2,%3}, {%4,%5,%6,%7}, {%8,%9}, {%0,%1,%2,%3};"
        : "+f"(c[0]), "+f"(c[1]), "+f"(c[2]), "+f"(c[3])
        : "r"(a[0]), "r"(a[1]), "r"(a[2]), "r"(a[3]), "r"(b0), "r"(b1));
}
__device__ __forceinline__ void split2(float x0, float x1,
                                       uint32_t& hi, uint32_t& lo) {
    __half h0 = __float2half_rn(x0), h1 = __float2half_rn(x1);
    __half l0 = __float2half_rn(x0 - __half2float(h0));
    __half l1 = __float2half_rn(x1 - __half2float(h1));
    __half2 hp = __halves2half2(h0, h1), lp = __halves2half2(l0, l1);
    hi = *reinterpret_cast<uint32_t*>(&hp);
    lo = *reinterpret_cast<uint32_t*>(&lp);
}
// byte offset in an f16 tile (256B rows), 16B-chunk XOR swizzle
__device__ __forceinline__ uint32_t swz(int row, int col) {
    return (uint32_t)(row * 256) + (uint32_t)((((col >> 3) ^ (row & 7)) & 15) << 4)
         + (uint32_t)((col & 7) << 1);
}
__device__ __forceinline__ uint32_t swz16(int row, int ch) {
    return (uint32_t)(row * 256) + (uint32_t)(((ch ^ (row & 7)) & 15) << 4);
}

// smem layout:
//   head h Q/P tiles (48 rows): PHI_h = h*24576, PLO_h = h*24576 + 12288
//   K tiles (96 rows): K-hi at 49152 (-> V head0), K-lo at 73728 (-> V head1)
#define SM_P0   0
#define SM_P1   24576
#define SM_KVHI 49152
#define SM_KLO  73728
#define SM_IDX  98304    /* 96 ints */
#define SM_ORD  98688
#define SM_RED  98816    /* per head 768B: redm[2][48], redl[2][48] */
#define SMEM_TOTAL 100352

// Dead-code-in-practice fallback for nc > 96 (slow, simple, correct).
__device__ __noinline__ void attn_fallback(int b, int c, int k, int nc,
                                           const int* idxs,
                                           const float* query,
                                           const float* value,
                                           float* out) {
    for (int r = threadIdx.x; r < nc; r += blockDim.x) {
        int i = idxs[r];
        const float* q = query + (((size_t)b * L_ + i) * V_ + k) * D_;
        float m = -1e30f;
        for (int jj = 0; jj < nc; jj++) {
            const float* kr = g_sumK + ((size_t)b * L_ + idxs[jj]) * D_;
            float s = 0.f;
            for (int d = 0; d < D_; d++) s += q[d] * kr[d];
            m = fmaxf(m, s * SCALE_);
        }
        float l = 0.f;
        for (int jj = 0; jj < nc; jj++) {
            const float* kr = g_sumK + ((size_t)b * L_ + idxs[jj]) * D_;
            float s = 0.f;
            for (int d = 0; d < D_; d++) s += q[d] * kr[d];
            l += __expf(s * SCALE_ - m);
        }
        for (int d0 = 0; d0 < D_; d0 += 32) {
            float acc[32];
            for (int e = 0; e < 32; e++) acc[e] = 0.f;
            for (int jj = 0; jj < nc; jj++) {
                const float* kr = g_sumK + ((size_t)b * L_ + idxs[jj]) * D_;
                float s = 0.f;
                for (int d = 0; d < D_; d++) s += q[d] * kr[d];
                float p = __expf(s * SCALE_ - m) / l;
                const float* vr = value +
                    (((size_t)b * L_ + idxs[jj]) * V_ + k) * D_ + d0;
                for (int e = 0; e < 32; e++) acc[e] += p * vr[e];
            }
            float* dst = out + (((size_t)b * L_ + i) * V_ + k) * D_ + d0;
            for (int e = 0; e < 32; e++) dst[e] = acc[e];
        }
    }
}

// ===========================================================================
// HMMA clustered attention: CTA = (head PAIR, cluster-rank, row-half of 48).
// 384 threads = 12 warps = 2 heads x (3 strips x 2 n/d-halves). K tiles are
// loaded once and shared by both heads; after S they hold the 2 V tiles.
// ===========================================================================
extern __shared__ char smx[];

__global__ void __launch_bounds__(384, 2)
attn_mma_kernel(const float* __restrict__ query,
                const float* __restrict__ value,
                float* __restrict__ out) {
    const int cl = blockIdx.y, z = blockIdx.z;
    const int tid = threadIdx.x;
    const int lane = tid & 31;
    const int w = tid >> 5;              // 0..11
    const int head = w >= 6;             // head within pair
    const int w6 = w - 6 * head;         // 0..5
    const int half = w6 & 1;
    const int sid = w6 >> 1;
    const int k = blockIdx.x * 2 + head; // global head

    // ---- LPT: rank clusters by descending count (deterministic tie-break)
    if (w == 0) {
        int key = -1;
        if (lane < 16) key = (g_cnt[lane >> 3][lane & 7] << 4) | (15 - lane);
        int rank = 0;
#pragma unroll
        for (int j = 0; j < 16; j++) {
            int other = __shfl_sync(0xffffffffu, key, j);
            if (lane < 16 && other > key) rank++;
        }
        if (lane < 16 && rank == cl) *(int*)(smx + SM_ORD) = lane;
    }
    __syncthreads();
    const int ordv = *(int*)(smx + SM_ORD);
    const int b = ordv >> 3, c = ordv & 7;

    const int nc = g_cnt[b][c];
    if (nc == 0) return;
    if (nc > NR_MAX) {
        if (z == 0) {
            attn_fallback(b, c, blockIdx.x * 2,     nc, g_idx[b][c], query, value, out);
            attn_fallback(b, c, blockIdx.x * 2 + 1, nc, g_idx[b][c], query, value, out);
        }
        return;
    }
    const int rowbase = z * 48;
    int nloc = nc - rowbase;
    if (nloc <= 0) return;
    if (nloc > 48) nloc = 48;

    int* idxs = (int*)(smx + SM_IDX);
    for (int t = tid; t < nc; t += 384) idxs[t] = g_idx[b][c][t];
    __syncthreads();

    const int nr = (nc + 15) & ~15;           // K/V rows, <= 96
    const int npair = nr >> 4;                // <= 6

    const uint32_t sb   = smem_u32(smx);
    const uint32_t phiT = sb + (head ? SM_P1 : SM_P0);
    const uint32_t ploT = phiT + 12288;
    const uint32_t kvh  = sb + SM_KVHI, klo = sb + SM_KLO;
    const uint32_t vT   = head ? klo : kvh;   // this head's V tile after S

    // ---- K (pre-split hi/lo) via cp.async — ONCE for both heads ----
    for (int t = tid; t < nr * 16; t += 384) {
        int row = t >> 4, ch = t & 15;
        uint32_t so = swz16(row, ch);
        if (row < nc) {
            size_t kb = (((size_t)b * L_ + idxs[row]) << 8) + (ch << 4);
            cpa16(kvh + so, (const char*)g_sKh + kb);
            cpa16(klo + so, (const char*)g_sKl + kb);
        } else {
            uint4 zz = make_uint4(0, 0, 0, 0);
            *(uint4*)(smx + SM_KVHI + so) = zz;
            *(uint4*)(smx + SM_KLO + so) = zz;
        }
    }
    asm volatile("cp.async.commit_group;");

    // ---- Q: direct LDG.128 -> split -> STS.64 into this head's tiles -----
#pragma unroll 1
    for (int batch = 0; batch < 2; batch++) {
        float4 qv[4];
#pragma unroll
        for (int i = 0; i < 4; i++) {
            int gr = rowbase + w6 + 6 * (4 * batch + i);
            if (gr < nc)
                qv[i] = ((const float4*)query)[
                    ((((size_t)b * L_ + idxs[gr]) * V_ + k) << 5) + lane];
        }
#pragma unroll
        for (int i = 0; i < 4; i++) {
            int lr = w6 + 6 * (4 * batch + i);
            uint32_t h0 = 0, l0 = 0, h1 = 0, l1 = 0;
            if (rowbase + lr < nc) {
                split2(qv[i].x * SCALE_, qv[i].y * SCALE_, h0, l0);
                split2(qv[i].z * SCALE_, qv[i].w * SCALE_, h1, l1);
            }
            uint32_t off = swz(lr, lane * 4);
            *(uint2*)((char*)smx + (phiT - sb) + off) = make_uint2(h0, h1);
            *(uint2*)((char*)smx + (ploT - sb) + off) = make_uint2(l0, l1);
        }
    }
    asm volatile("cp.async.wait_group 0;" ::: "memory");
    __syncthreads();

    float* redm = (float*)(smx + SM_RED + head * 768);   // [2][48]
    float* redl = redm + 96;

    const int g  = lane >> 3;
    const int rA = (lane & 7) + ((g & 1) << 3);
    const int cA = ((g >> 1) & 1) << 3;
    const int rB = (lane & 7) + (((g >> 1) & 1) << 3);
    const int cB = (g & 1) << 3;
    const int colb = (lane & 3) << 1;
    const int qr = lane >> 2;

    const int lr0 = sid * 16;
    const bool active = lr0 < nloc;
    const int r1 = lr0 + qr, r2 = r1 + 8;     // local P rows

    // ================= S = Q * Ksum^T (full 3-term) ====================
    float cS[6][4];
#pragma unroll
    for (int n = 0; n < 6; n++)
#pragma unroll
        for (int r = 0; r < 4; r++) cS[n][r] = 0.f;

    if (active) {
#pragma unroll
        for (int s = 0; s < 8; s++) {
            uint32_t ah[4], al[4], bh[3][4], bl[3][4];
            ldsm4(phiT + swz(lr0 + rA, s * 16 + cA), ah);
            ldsm4(ploT + swz(lr0 + rA, s * 16 + cA), al);
#pragma unroll
            for (int u = 0; u < 3; u++) {
                int ti = half + 2 * u;
                if (ti < npair) {
                    ldsm4(kvh + swz(16 * ti + rB, s * 16 + cB), bh[u]);
                    ldsm4(klo + swz(16 * ti + rB, s * 16 + cB), bl[u]);
                }
            }
#pragma unroll
            for (int u = 0; u < 3; u++)
                if (half + 2 * u < npair) {
                    mma16816(cS[2 * u],     ah, bh[u][0], bh[u][1]);
                    mma16816(cS[2 * u + 1], ah, bh[u][2], bh[u][3]);
                }
#pragma unroll
            for (int u = 0; u < 3; u++)
                if (half + 2 * u < npair) {
                    mma16816(cS[2 * u],     ah, bl[u][0], bl[u][1]);
                    mma16816(cS[2 * u + 1], ah, bl[u][2], bl[u][3]);
                }
#pragma unroll
            for (int u = 0; u < 3; u++)
                if (half + 2 * u < npair) {
                    mma16816(cS[2 * u],     al, bh[u][0], bh[u][1]);
                    mma16816(cS[2 * u + 1], al, bh[u][2], bh[u][3]);
                }
        }

        float m0 = -1e30f, m1 = -1e30f;
#pragma unroll
        for (int u = 0; u < 3; u++) {
            int ti = half + 2 * u;
            if (ti < npair) {
#pragma unroll
                for (int sub = 0; sub < 2; sub++) {
                    int n = 2 * u + sub;
                    int c0 = ti * 16 + sub * 8 + colb;
                    if (c0 < nc)     { m0 = fmaxf(m0, cS[n][0]); m1 = fmaxf(m1, cS[n][2]); }
                    if (c0 + 1 < nc) { m0 = fmaxf(m0, cS[n][1]); m1 = fmaxf(m1, cS[n][3]); }
                }
            }
        }
        m0 = fmaxf(m0, __shfl_xor_sync(0xffffffffu, m0, 1));
        m0 = fmaxf(m0, __shfl_xor_sync(0xffffffffu, m0, 2));
        m1 = fmaxf(m1, __shfl_xor_sync(0xffffffffu, m1, 1));
        m1 = fmaxf(m1, __shfl_xor_sync(0xffffffffu, m1, 2));
        if ((lane & 3) == 0) {
            redm[half * 48 + r1] = m0;
            redm[half * 48 + r2] = m1;
        }
    }
    __syncthreads();   // all K ldsm done (K tiles dead) + partial maxes visible

    // ---- softmax: exp, P (hi only) -> this head's P tile, partial l ------
    if (active) {
        float mt0 = fmaxf(redm[r1], redm[48 + r1]);
        float mt1 = fmaxf(redm[r2], redm[48 + r2]);
        float l0 = 0.f, l1 = 0.f;
#pragma unroll
        for (int u = 0; u < 3; u++) {
            int ti = half + 2 * u;
            if (ti < npair) {
#pragma unroll
                for (int sub = 0; sub < 2; sub++) {
                    int n = 2 * u + sub;
                    int c0 = ti * 16 + sub * 8 + colb;
                    float p0 = (c0     < nc) ? __expf(cS[n][0] - mt0) : 0.f;
                    float p1 = (c0 + 1 < nc) ? __expf(cS[n][1] - mt0) : 0.f;
                    float p2 = (c0     < nc) ? __expf(cS[n][2] - mt1) : 0.f;
                    float p3 = (c0 + 1 < nc) ? __expf(cS[n][3] - mt1) : 0.f;
                    l0 += p0 + p1; l1 += p2 + p3;
                    *(uint32_t*)((char*)smx + (phiT - sb) + swz(r1, c0)) = packh2(p0, p1);
                    *(uint32_t*)((char*)smx + (phiT - sb) + swz(r2, c0)) = packh2(p2, p3);
                }
            }
        }
        l0 += __shfl_xor_sync(0xffffffffu, l0, 1);
        l0 += __shfl_xor_sync(0xffffffffu, l0, 2);
        l1 += __shfl_xor_sync(0xffffffffu, l1, 1);
        l1 += __shfl_xor_sync(0xffffffffu, l1, 2);
        if ((lane & 3) == 0) {
            redl[half * 48 + r1] = l0;
            redl[half * 48 + r2] = l1;
        }
    }

    // ---- V: this head's rows [0,96) -> fp16 hi into its V tile -----------
    {
        float4 va[8];
#pragma unroll
        for (int i = 0; i < 8; i++) {
            int row = w6 + 6 * i;         // 0..47
            if (row < nc)
                va[i] = ((const float4*)value)[
                    ((((size_t)b * L_ + idxs[row]) * V_ + k) << 5) + lane];
        }
        __syncthreads();   // K tiles fully dead across CTA; P/l written
#pragma unroll
        for (int i = 0; i < 8; i++) {
            int row = w6 + 6 * i;
            uint32_t h0 = 0, h1 = 0;
            if (row < nc) {
                h0 = packh2(va[i].x, va[i].y);
                h1 = packh2(va[i].z, va[i].w);
            }
            if (row < nr)
                *(uint2*)((char*)smx + (vT - sb) + swz(row, lane * 4)) = make_uint2(h0, h1);
        }
        float4 vbB[8];
#pragma unroll
        for (int i = 0; i < 8; i++) {
            int row = 48 + w6 + 6 * i;    // 48..95
            if (row < nc)
                vbB[i] = ((const float4*)value)[
                    ((((size_t)b * L_ + idxs[row]) * V_ + k) << 5) + lane];
        }
#pragma unroll
        for (int i = 0; i < 8; i++) {
            int row = 48 + w6 + 6 * i;
            uint32_t h0 = 0, h1 = 0;
            if (row < nc) {
                h0 = packh2(vbB[i].x, vbB[i].y);
                h1 = packh2(vbB[i].z, vbB[i].w);
            }
            if (row < nr)
                *(uint2*)((char*)smx + (vT - sb) + swz(row, lane * 4)) = make_uint2(h0, h1);
        }
    }
    __syncthreads();   // both V tiles complete

    // ================= O = Phi * Vhi  (d-range = half*64..+63) =============
    if (active) {
        float o[8][4];
#pragma unroll
        for (int n = 0; n < 8; n++)
#pragma unroll
            for (int r = 0; r < 4; r++) o[n][r] = 0.f;

#pragma unroll
        for (int kt = 0; kt < 6; kt++) {
            if (kt < npair) {
                uint32_t ph[4], vh[4][4];
                ldsm4(phiT + swz(lr0 + rA, kt * 16 + cA), ph);
#pragma unroll
                for (int dq = 0; dq < 4; dq++) {
                    int dp = half * 4 + dq;
                    ldsm4t(vT + swz(16 * kt + rA, 16 * dp + cA), vh[dq]);
                }
#pragma unroll
                for (int dq = 0; dq < 4; dq++) {
                    mma16816(o[2 * dq],     ph, vh[dq][0], vh[dq][1]);
                    mma16816(o[2 * dq + 1], ph, vh[dq][2], vh[dq][3]);
                }
            }
        }

        // ---- epilogue
        float lt0 = redl[r1] + redl[48 + r1];
        float lt1 = redl[r2] + redl[48 + r2];
        float i0 = 1.f / lt0, i1 = 1.f / lt1;
        int gr1 = rowbase + r1, gr2 = rowbase + r2;
        float* d1 = (gr1 < nc)
            ? out + (((size_t)b * L_ + idxs[gr1]) * V_ + k) * D_ : nullptr;
        float* d2 = (gr2 < nc)
            ? out + (((size_t)b * L_ + idxs[gr2]) * V_ + k) * D_ : nullptr;
#pragma unroll
        for (int n = 0; n < 8; n++) {
            int col = half * 64 + (n >> 1) * 16 + (n & 1) * 8 + colb;
            if (d1) *(float2*)(d1 + col) = make_float2(o[n][0] * i0, o[n][1] * i0);
            if (d2) *(float2*)(d2 + col) = make_float2(o[n][2] * i1, o[n][3] * i1);
        }
    }
}

extern "C" void kernel_launch(void* const* d_in, const int* in_sizes, int n_in,
                              void* d_out, int out_size) {
    (void)in_sizes; (void)n_in; (void)out_size;
    const float* query = (const float*)d_in[0];
    const float* key   = (const float*)d_in[1];
    const float* value = (const float*)d_in[2];
    const int*   label = (const int*)d_in[3];
    float* out = (float*)d_out;

    prep_kernel<<<1040, 256>>>((const float4*)key, label);
    cudaFuncSetAttribute(attn_mma_kernel,
                         cudaFuncAttributeMaxDynamicSharedMemorySize, SMEM_TOTAL);
    attn_mma_kernel<<<dim3(V_ / 2, 16, 2), 384, SMEM_TOTAL>>>(query, value, out);
}

// round 16
// speedup vs baseline: 1.0339x; 1.0339x over previous
#include <cuda_runtime.h>
#include <cuda_fp16.h>
#include <cstdint>

#define B_ 2
#define L_ 512
#define V_ 64
#define D_ 128
#define NC_ 8
#define NR_MAX 96

// ---- static device scratch (no allocations allowed) ----
__device__ float  g_sumK[B_ * L_ * D_];
__device__ __half g_sKh[B_ * L_ * D_];
__device__ __half g_sKl[B_ * L_ * D_];
__device__ int    g_idx[B_][NC_][L_];
__device__ int    g_cnt[B_][NC_];

#define SCALE_ 0.08838834764831845f

__device__ __forceinline__ uint32_t packh2(float a, float b2) {
    __half2 h = __halves2half2(__float2half_rn(a), __float2half_rn(b2));
    return *reinterpret_cast<uint32_t*>(&h);
}

// ===========================================================================
// Prep kernel: blocks [0,1024) sumK (+fp16 hi/lo); [1024,1040) idx lists
// ===========================================================================
__global__ void prep_kernel(const float4* __restrict__ key4,
                            const int* __restrict__ label) {
    __shared__ float4 part[256];
    const int blk = blockIdx.x;

    if (blk < 1024) {
        int bl = blk;
        int g = threadIdx.x & 31, qd = threadIdx.x >> 5;
        const float4* p = key4 + (size_t)bl * (V_ * D_ / 4)
                        + (size_t)(qd * 8) * (D_ / 4) + g;
        float4 s = make_float4(0.f, 0.f, 0.f, 0.f);
#pragma unroll
        for (int vv = 0; vv < 8; vv++) {
            float4 t = p[(size_t)vv * (D_ / 4)];
            s.x += t.x; s.y += t.y; s.z += t.z; s.w += t.w;
        }
        part[threadIdx.x] = s;
        __syncthreads();
        if (qd < 4) {
            float4 a = part[threadIdx.x], b2 = part[threadIdx.x + 128];
            part[threadIdx.x] =
                make_float4(a.x + b2.x, a.y + b2.y, a.z + b2.z, a.w + b2.w);
        }
        __syncthreads();
        if (qd == 0) {
            float4 a = part[g], b2 = part[32 + g], c2 = part[64 + g], d2 = part[96 + g];
            float4 r = make_float4(a.x + b2.x + c2.x + d2.x, a.y + b2.y + c2.y + d2.y,
                                   a.z + b2.z + c2.z + d2.z, a.w + b2.w + c2.w + d2.w);
            ((float4*)g_sumK)[(size_t)bl * 32 + g] = r;
            __half hx = __float2half_rn(r.x), hy = __float2half_rn(r.y);
            __half hz = __float2half_rn(r.z), hw = __float2half_rn(r.w);
            size_t o = (size_t)bl * 64 + g * 2;
            { __half2 t = __halves2half2(hx, hy); ((uint32_t*)g_sKh)[o] = *(uint32_t*)&t; }
            { __half2 t = __halves2half2(hz, hw); ((uint32_t*)g_sKh)[o + 1] = *(uint32_t*)&t; }
            ((uint32_t*)g_sKl)[o] =
                packh2(r.x - __half2float(hx), r.y - __half2float(hy));
            ((uint32_t*)g_sKl)[o + 1] =
                packh2(r.z - __half2float(hz), r.w - __half2float(hw));
        }
    } else {
        if (threadIdx.x >= 32) return;
        int bc = blk - 1024;
        int c = bc & 7, b = bc >> 3;
        int lane = threadIdx.x;
        int cnt = 0;
        for (int l0 = 0; l0 < L_; l0 += 32) {
            int l = l0 + lane;
            int lbl = label[b * L_ + l];
            unsigned m = __ballot_sync(0xffffffffu, lbl == c);
            if (lbl == c) {
                int pos = cnt + __popc(m & ((1u << lane) - 1u));
                g_idx[b][c][pos] = l;
            }
            cnt += __popc(m);
        }
        if (lane == 0) g_cnt[b][c] = cnt;
    }
}

// ===========================================================================
// PTX helpers (family-common, valid on target sm_103)
// ===========================================================================
__device__ __forceinline__ uint32_t smem_u32(const void* p) {
    uint32_t a;
    asm("{ .reg .u64 t; cvta.to.shared.u64 t, %1; cvt.u32.u64 %0, t; }"
        : "=r"(a) : "l"(p));
    return a;
}
__device__ __forceinline__ void cpa16(uint32_t dst, const void* src) {
    asm volatile("cp.async.cg.shared.global [%0], [%1], 16;"
                 :: "r"(dst), "l"(src));
}
__device__ __forceinline__ void ldsm4(uint32_t addr, uint32_t* r) {
    asm volatile("ldmatrix.sync.aligned.m8n8.x4.shared.b16 {%0,%1,%2,%3}, [%4];"
                 : "=r"(r[0]), "=r"(r[1]), "=r"(r[2]), "=r"(r[3]) : "r"(addr));
}
__device__ __forceinline__ void ldsm4t(uint32_t addr, uint32_t* r) {
    asm volatile("ldmatrix.sync.aligned.m8n8.x4.trans.shared.b16 {%0,%1,%2,%3}, [%4];"
                 : "=r"(r[0]), "=r"(r[1]), "=r"(r[2]), "=r"(r[3]) : "r"(addr));
}
__device__ __forceinline__ void mma16816(float* c, const uint32_t* a,
                                         uint32_t b0, uint32_t b1) {
    asm volatile(
        "mma.sync.aligned.m16n8k16.row.col.f32.f16.f16.f32 "
        "{%0,%1,%2,%3}, {%4,%5,%6,%7}, {%8,%9}, {%0,%1,%2,%3};"
        : "+f"(c[0]), "+f"(c[1]), "+f"(c[2]), "+f"(c[3])
        : "r"(a[0]), "r"(a[1]), "r"(a[2]), "r"(a[3]), "r"(b0), "r"(b1));
}
__device__ __forceinline__ void split2(float x0, float x1,
                                       uint32_t& hi, uint32_t& lo) {
    __half h0 = __float2half_rn(x0), h1 = __float2half_rn(x1);
    __half l0 = __float2half_rn(x0 - __half2float(h0));
    __half l1 = __float2half_rn(x1 - __half2float(h1));
    __half2 hp = __halves2half2(h0, h1), lp = __halves2half2(l0, l1);
    hi = *reinterpret_cast<uint32_t*>(&hp);
    lo = *reinterpret_cast<uint32_t*>(&lp);
}
// byte offset in an f16 tile (256B rows), 16B-chunk XOR swizzle
__device__ __forceinline__ uint32_t swz(int row, int col) {
    return (uint32_t)(row * 256) + (uint32_t)((((col >> 3) ^ (row & 7)) & 15) << 4)
         + (uint32_t)((col & 7) << 1);
}
__device__ __forceinline__ uint32_t swz16(int row, int ch) {
    return (uint32_t)(row * 256) + (uint32_t)(((ch ^ (row & 7)) & 15) << 4);
}

// smem layout: P tiles 48 rows; K hi/lo tiles 96 rows; V (hi-only) over K-hi
#define SM_PHI  0
#define SM_PLO  12288
#define SM_KVHI 24576
#define SM_KLO  49152
#define SM_IDX  73728    /* 96 ints */
#define SM_RED  74240    /* redm[2][48], redl[2][48] */
#define SMEM_TOTAL 75008

// Dead-code-in-practice fallback for nc > 96 (slow, simple, correct).
__device__ __noinline__ void attn_fallback(int b, int c, int k, int nc,
                                           const int* idxs,
                                           const float* query,
                                           const float* value,
                                           float* out) {
    for (int r = threadIdx.x; r < nc; r += blockDim.x) {
        int i = idxs[r];
        const float* q = query + (((size_t)b * L_ + i) * V_ + k) * D_;
        float m = -1e30f;
        for (int jj = 0; jj < nc; jj++) {
            const float* kr = g_sumK + ((size_t)b * L_ + idxs[jj]) * D_;
            float s = 0.f;
            for (int d = 0; d < D_; d++) s += q[d] * kr[d];
            m = fmaxf(m, s * SCALE_);
        }
        float l = 0.f;
        for (int jj = 0; jj < nc; jj++) {
            const float* kr = g_sumK + ((size_t)b * L_ + idxs[jj]) * D_;
            float s = 0.f;
            for (int d = 0; d < D_; d++) s += q[d] * kr[d];
            l += __expf(s * SCALE_ - m);
        }
        for (int d0 = 0; d0 < D_; d0 += 32) {
            float acc[32];
            for (int e = 0; e < 32; e++) acc[e] = 0.f;
            for (int jj = 0; jj < nc; jj++) {
                const float* kr = g_sumK + ((size_t)b * L_ + idxs[jj]) * D_;
                float s = 0.f;
                for (int d = 0; d < D_; d++) s += q[d] * kr[d];
                float p = __expf(s * SCALE_ - m) / l;
                const float* vr = value +
                    (((size_t)b * L_ + idxs[jj]) * V_ + k) * D_ + d0;
                for (int e = 0; e < 32; e++) acc[e] += p * vr[e];
            }
            float* dst = out + (((size_t)b * L_ + i) * V_ + k) * D_ + d0;
            for (int e = 0; e < 32; e++) dst[e] = acc[e];
        }
    }
}

// ===========================================================================
// HMMA clustered attention (R12 structure): CTA = (head, cluster-rank, z-half
// of 48 rows). 192 threads = 3 strips x 2 n/d-halves. 3 CTAs/SM. 3 barriers.
// ===========================================================================
extern __shared__ char smx[];

__global__ void __launch_bounds__(192, 3)
attn_mma_kernel(const float* __restrict__ query,
                const float* __restrict__ value,
                float* __restrict__ out) {
    const int k = blockIdx.x, cl = blockIdx.y, z = blockIdx.z;
    const int tid = threadIdx.x;
    const int lane = tid & 31;
    const int w = tid >> 5;          // 0..5
    const int half = w & 1;
    const int sid = w >> 1;          // strip 0..2

    // ---- LPT: every warp ranks clusters by descending count (no smem/bar)
    int ordv;
    {
        int key = (lane < 16)
                ? ((g_cnt[lane >> 3][lane & 7] << 4) | (15 - lane)) : -1;
        int rank = 0;
#pragma unroll
        for (int j = 0; j < 16; j++) {
            int other = __shfl_sync(0xffffffffu, key, j);
            if (other > key) rank++;
        }
        unsigned m = __ballot_sync(0xffffffffu, lane < 16 && rank == cl);
        ordv = __ffs(m) - 1;
    }
    const int b = ordv >> 3, c = ordv & 7;
    const int* __restrict__ gidx = g_idx[b][c];

    const int nc = g_cnt[b][c];
    if (nc == 0) return;
    if (nc > NR_MAX) {
        if (z == 0) attn_fallback(b, c, k, nc, gidx, query, value, out);
        return;
    }
    const int rowbase = z * 48;
    int nloc = nc - rowbase;
    if (nloc <= 0) return;
    if (nloc > 48) nloc = 48;

    const int nr = (nc + 15) & ~15;           // K/V rows, <= 96
    const int npair = nr >> 4;                // <= 6

    const uint32_t sb  = smem_u32(smx);
    const uint32_t phi = sb + SM_PHI, plo = sb + SM_PLO;
    const uint32_t kvh = sb + SM_KVHI, klo = sb + SM_KLO;
    int* idxs = (int*)(smx + SM_IDX);

    // ---- idx -> smem (visible after the fill barrier; fills use g_idx) ---
    for (int t = tid; t < nc; t += 192) idxs[t] = gidx[t];

    // ---- K (pre-split hi/lo) via cp.async, addresses from g_idx ----------
    for (int t = tid; t < nr * 16; t += 192) {
        int row = t >> 4, ch = t & 15;
        uint32_t so = swz16(row, ch);
        if (row < nc) {
            size_t kb = (((size_t)b * L_ + gidx[row]) << 8) + (ch << 4);
            cpa16(kvh + so, (const char*)g_sKh + kb);
            cpa16(klo + so, (const char*)g_sKl + kb);
        } else {
            uint4 zz = make_uint4(0, 0, 0, 0);
            *(uint4*)(smx + SM_KVHI + so) = zz;
            *(uint4*)(smx + SM_KLO + so) = zz;
        }
    }
    asm volatile("cp.async.commit_group;");

    // ---- Q: direct LDG.128 (one row per warp-inst) -> split -> STS.64 ----
    {
        float4 qv[8];
#pragma unroll
        for (int i = 0; i < 8; i++) {
            int gr = rowbase + w + 6 * i;
            if (gr < nc)
                qv[i] = ((const float4*)query)[
                    ((((size_t)b * L_ + gidx[gr]) * V_ + k) << 5) + lane];
        }
#pragma unroll
        for (int i = 0; i < 8; i++) {
            int lr = w + 6 * i;
            int gr = rowbase + lr;
            uint32_t h0 = 0, l0 = 0, h1 = 0, l1 = 0;
            if (gr < nc) {
                split2(qv[i].x * SCALE_, qv[i].y * SCALE_, h0, l0);
                split2(qv[i].z * SCALE_, qv[i].w * SCALE_, h1, l1);
            }
            uint32_t off = swz(lr, lane * 4);   // cols 4L..4L+3 share a chunk
            *(uint2*)(smx + SM_PHI + off) = make_uint2(h0, h1);
            *(uint2*)(smx + SM_PLO + off) = make_uint2(l0, l1);
        }
    }
    asm volatile("cp.async.wait_group 0;" ::: "memory");
    __syncthreads();   // [bar 1] fills + idxs visible

    float* redm = (float*)(smx + SM_RED);     // [2][48]
    float* redl = redm + 96;

    const int g  = lane >> 3;
    const int rA = (lane & 7) + ((g & 1) << 3);
    const int cA = ((g >> 1) & 1) << 3;
    const int rB = (lane & 7) + (((g >> 1) & 1) << 3);
    const int cB = (g & 1) << 3;
    const int colb = (lane & 3) << 1;
    const int qr = lane >> 2;

    const int lr0 = sid * 16;
    const bool active = lr0 < nloc;
    const int r1 = lr0 + qr, r2 = r1 + 8;     // local P rows

    // ================= S = Q * Ksum^T (full 3-term) ====================
    float cS[6][4];
#pragma unroll
    for (int n = 0; n < 6; n++)
#pragma unroll
        for (int r = 0; r < 4; r++) cS[n][r] = 0.f;

    if (active) {
#pragma unroll
        for (int s = 0; s < 8; s++) {
            uint32_t ah[4], al[4], bh[3][4], bl[3][4];
            ldsm4(phi + swz(lr0 + rA, s * 16 + cA), ah);
            ldsm4(plo + swz(lr0 + rA, s * 16 + cA), al);
#pragma unroll
            for (int u = 0; u < 3; u++) {
                int ti = half + 2 * u;
                if (ti < npair) {
                    ldsm4(kvh + swz(16 * ti + rB, s * 16 + cB), bh[u]);
                    ldsm4(klo + swz(16 * ti + rB, s * 16 + cB), bl[u]);
                }
            }
#pragma unroll
            for (int u = 0; u < 3; u++)
                if (half + 2 * u < npair) {
                    mma16816(cS[2 * u],     ah, bh[u][0], bh[u][1]);
                    mma16816(cS[2 * u + 1], ah, bh[u][2], bh[u][3]);
                }
#pragma unroll
            for (int u = 0; u < 3; u++)
                if (half + 2 * u < npair) {
                    mma16816(cS[2 * u],     ah, bl[u][0], bl[u][1]);
                    mma16816(cS[2 * u + 1], ah, bl[u][2], bl[u][3]);
                }
#pragma unroll
            for (int u = 0; u < 3; u++)
                if (half + 2 * u < npair) {
                    mma16816(cS[2 * u],     al, bh[u][0], bh[u][1]);
                    mma16816(cS[2 * u + 1], al, bh[u][2], bh[u][3]);
                }
        }

        float m0 = -1e30f, m1 = -1e30f;
#pragma unroll
        for (int u = 0; u < 3; u++) {
            int ti = half + 2 * u;
            if (ti < npair) {
#pragma unroll
                for (int sub = 0; sub < 2; sub++) {
                    int n = 2 * u + sub;
                    int c0 = ti * 16 + sub * 8 + colb;
                    if (c0 < nc)     { m0 = fmaxf(m0, cS[n][0]); m1 = fmaxf(m1, cS[n][2]); }
                    if (c0 + 1 < nc) { m0 = fmaxf(m0, cS[n][1]); m1 = fmaxf(m1, cS[n][3]); }
                }
            }
        }
        m0 = fmaxf(m0, __shfl_xor_sync(0xffffffffu, m0, 1));
        m0 = fmaxf(m0, __shfl_xor_sync(0xffffffffu, m0, 2));
        m1 = fmaxf(m1, __shfl_xor_sync(0xffffffffu, m1, 1));
        m1 = fmaxf(m1, __shfl_xor_sync(0xffffffffu, m1, 2));
        if ((lane & 3) == 0) {
            redm[half * 48 + r1] = m0;
            redm[half * 48 + r2] = m1;
        }
    }
    __syncthreads();   // [bar 2] K ldsm done (K tiles dead) + partial maxes

    // ---- V batch A: direct LDG of rows [0,48) (latency hidden by softmax)
    float4 va[8];
#pragma unroll
    for (int i = 0; i < 8; i++) {
        int row = w + 6 * i;              // 0..47
        if (row < nc)
            va[i] = ((const float4*)value)[
                ((((size_t)b * L_ + idxs[row]) * V_ + k) << 5) + lane];
    }

    // ---- softmax: exp, P (hi only) -> smem, partial l --------------------
    if (active) {
        float mt0 = fmaxf(redm[r1], redm[48 + r1]);
        float mt1 = fmaxf(redm[r2], redm[48 + r2]);
        float l0 = 0.f, l1 = 0.f;
#pragma unroll
        for (int u = 0; u < 3; u++) {
            int ti = half + 2 * u;
            if (ti < npair) {
#pragma unroll
                for (int sub = 0; sub < 2; sub++) {
                    int n = 2 * u + sub;
                    int c0 = ti * 16 + sub * 8 + colb;
                    float p0 = (c0     < nc) ? __expf(cS[n][0] - mt0) : 0.f;
                    float p1 = (c0 + 1 < nc) ? __expf(cS[n][1] - mt0) : 0.f;
                    float p2 = (c0     < nc) ? __expf(cS[n][2] - mt1) : 0.f;
                    float p3 = (c0 + 1 < nc) ? __expf(cS[n][3] - mt1) : 0.f;
                    l0 += p0 + p1; l1 += p2 + p3;
                    *(uint32_t*)(smx + SM_PHI + swz(r1, c0)) = packh2(p0, p1);
                    *(uint32_t*)(smx + SM_PHI + swz(r2, c0)) = packh2(p2, p3);
                }
            }
        }
        l0 += __shfl_xor_sync(0xffffffffu, l0, 1);
        l0 += __shfl_xor_sync(0xffffffffu, l0, 2);
        l1 += __shfl_xor_sync(0xffffffffu, l1, 1);
        l1 += __shfl_xor_sync(0xffffffffu, l1, 2);
        if ((lane & 3) == 0) {
            redl[half * 48 + r1] = l0;
            redl[half * 48 + r2] = l1;
        }
    }

    // ---- V batch B LDG (rows [48,96)), then store both batches as fp16 hi
    {
        float4 vbB[8];
#pragma unroll
        for (int i = 0; i < 8; i++) {
            int row = 48 + w + 6 * i;     // 48..95
            if (row < nc)
                vbB[i] = ((const float4*)value)[
                    ((((size_t)b * L_ + idxs[row]) * V_ + k) << 5) + lane];
        }
#pragma unroll
        for (int i = 0; i < 8; i++) {
            int row = w + 6 * i;
            uint32_t h0 = 0, h1 = 0;
            if (row < nc) {
                h0 = packh2(va[i].x, va[i].y);
                h1 = packh2(va[i].z, va[i].w);
            }
            if (row < nr)
                *(uint2*)(smx + SM_KVHI + swz(row, lane * 4)) = make_uint2(h0, h1);
        }
#pragma unroll
        for (int i = 0; i < 8; i++) {
            int row = 48 + w + 6 * i;
            uint32_t h0 = 0, h1 = 0;
            if (row < nc) {
                h0 = packh2(vbB[i].x, vbB[i].y);
                h1 = packh2(vbB[i].z, vbB[i].w);
            }
            if (row < nr)
                *(uint2*)(smx + SM_KVHI + swz(row, lane * 4)) = make_uint2(h0, h1);
        }
    }
    __syncthreads();   // [bar 3] V tile + P tiles + partial l complete

    // ================= O = Phi * Vhi  (d-range = half*64..+63) =============
    if (active) {
        float o[8][4];
#pragma unroll
        for (int n = 0; n < 8; n++)
#pragma unroll
            for (int r = 0; r < 4; r++) o[n][r] = 0.f;

#pragma unroll
        for (int kt = 0; kt < 6; kt++) {
            if (kt < npair) {
                uint32_t ph[4], vh[4][4];
                ldsm4(phi + swz(lr0 + rA, kt * 16 + cA), ph);
#pragma unroll
                for (int dq = 0; dq < 4; dq++) {
                    int dp = half * 4 + dq;
                    ldsm4t(kvh + swz(16 * kt + rA, 16 * dp + cA), vh[dq]);
                }
#pragma unroll
                for (int dq = 0; dq < 4; dq++) {
                    mma16816(o[2 * dq],     ph, vh[dq][0], vh[dq][1]);
                    mma16816(o[2 * dq + 1], ph, vh[dq][2], vh[dq][3]);
                }
            }
        }

        // ---- epilogue
        float lt0 = redl[r1] + redl[48 + r1];
        float lt1 = redl[r2] + redl[48 + r2];
        float i0 = 1.f / lt0, i1 = 1.f / lt1;
        int gr1 = rowbase + r1, gr2 = rowbase + r2;
        float* d1 = (gr1 < nc)
            ? out + (((size_t)b * L_ + idxs[gr1]) * V_ + k) * D_ : nullptr;
        float* d2 = (gr2 < nc)
            ? out + (((size_t)b * L_ + idxs[gr2]) * V_ + k) * D_ : nullptr;
#pragma unroll
        for (int n = 0; n < 8; n++) {
            int col = half * 64 + (n >> 1) * 16 + (n & 1) * 8 + colb;
            if (d1) *(float2*)(d1 + col) = make_float2(o[n][0] * i0, o[n][1] * i0);
            if (d2) *(float2*)(d2 + col) = make_float2(o[n][2] * i1, o[n][3] * i1);
        }
    }
}

extern "C" void kernel_launch(void* const* d_in, const int* in_sizes, int n_in,
                              void* d_out, int out_size) {
    (void)in_sizes; (void)n_in; (void)out_size;
    const float* query = (const float*)d_in[0];
    const float* key   = (const float*)d_in[1];
    const float* value = (const float*)d_in[2];
    const int*   label = (const int*)d_in[3];
    float* out = (float*)d_out;

    prep_kernel<<<1040, 256>>>((const float4*)key, label);
    cudaFuncSetAttribute(attn_mma_kernel,
                         cudaFuncAttributeMaxDynamicSharedMemorySize, SMEM_TOTAL);
    attn_mma_kernel<<<dim3(V_, 16, 2), 192, SMEM_TOTAL>>>(query, value, out);
}

// round 17
// speedup vs baseline: 1.0625x; 1.0277x over previous
#include <cuda_runtime.h>
#include <cuda_fp16.h>
#include <cstdint>

#define B_ 2
#define L_ 512
#define V_ 64
#define D_ 128
#define NC_ 8
#define NR_MAX 96

// ---- static device scratch (no allocations allowed) ----
__device__ float  g_sumK[B_ * L_ * D_];
__device__ __half g_sKh[B_ * L_ * D_];
__device__ __half g_sKl[B_ * L_ * D_];
__device__ int    g_idx[B_][NC_][L_];
__device__ int    g_cnt[B_][NC_];

#define SCALE_ 0.08838834764831845f

__device__ __forceinline__ uint32_t packh2(float a, float b2) {
    __half2 h = __halves2half2(__float2half_rn(a), __float2half_rn(b2));
    return *reinterpret_cast<uint32_t*>(&h);
}

// ===========================================================================
// Prep kernel (512 threads): blocks [0,1024) sumK; [1024,1040) idx lists
// ===========================================================================
__global__ void prep_kernel(const float4* __restrict__ key4,
                            const int* __restrict__ label) {
    __shared__ float4 part[512];
    const int blk = blockIdx.x;

    if (blk < 1024) {
        int bl = blk;
        int g = threadIdx.x & 31, qd = threadIdx.x >> 5;   // qd 0..15
        const float4* p = key4 + (size_t)bl * (V_ * D_ / 4)
                        + (size_t)(qd * 4) * (D_ / 4) + g;
        float4 s = make_float4(0.f, 0.f, 0.f, 0.f);
#pragma unroll
        for (int vv = 0; vv < 4; vv++) {
            float4 t = p[(size_t)vv * (D_ / 4)];
            s.x += t.x; s.y += t.y; s.z += t.z; s.w += t.w;
        }
        part[threadIdx.x] = s;
        __syncthreads();
        if (qd < 8) {
            float4 a = part[threadIdx.x], b2 = part[threadIdx.x + 256];
            part[threadIdx.x] =
                make_float4(a.x + b2.x, a.y + b2.y, a.z + b2.z, a.w + b2.w);
        }
        __syncthreads();
        if (qd < 4) {
            float4 a = part[threadIdx.x], b2 = part[threadIdx.x + 128];
            part[threadIdx.x] =
                make_float4(a.x + b2.x, a.y + b2.y, a.z + b2.z, a.w + b2.w);
        }
        __syncthreads();
        if (qd == 0) {
            float4 a = part[g], b2 = part[32 + g], c2 = part[64 + g], d2 = part[96 + g];
            float4 r = make_float4(a.x + b2.x + c2.x + d2.x, a.y + b2.y + c2.y + d2.y,
                                   a.z + b2.z + c2.z + d2.z, a.w + b2.w + c2.w + d2.w);
            ((float4*)g_sumK)[(size_t)bl * 32 + g] = r;
            __half hx = __float2half_rn(r.x), hy = __float2half_rn(r.y);
            __half hz = __float2half_rn(r.z), hw = __float2half_rn(r.w);
            size_t o = (size_t)bl * 64 + g * 2;
            { __half2 t = __halves2half2(hx, hy); ((uint32_t*)g_sKh)[o] = *(uint32_t*)&t; }
            { __half2 t = __halves2half2(hz, hw); ((uint32_t*)g_sKh)[o + 1] = *(uint32_t*)&t; }
            ((uint32_t*)g_sKl)[o] =
                packh2(r.x - __half2float(hx), r.y - __half2float(hy));
            ((uint32_t*)g_sKl)[o + 1] =
                packh2(r.z - __half2float(hz), r.w - __half2float(hw));
        }
    } else {
        if (threadIdx.x >= 32) return;
        int bc = blk - 1024;
        int c = bc & 7, b = bc >> 3;
        int lane = threadIdx.x;
        int cnt = 0;
        for (int l0 = 0; l0 < L_; l0 += 32) {
            int l = l0 + lane;
            int lbl = label[b * L_ + l];
            unsigned m = __ballot_sync(0xffffffffu, lbl == c);
            if (lbl == c) {
                int pos = cnt + __popc(m & ((1u << lane) - 1u));
                g_idx[b][c][pos] = l;
            }
            cnt += __popc(m);
        }
        if (lane == 0) g_cnt[b][c] = cnt;
    }
}

// ===========================================================================
// PTX helpers (family-common, valid on target sm_103)
// ===========================================================================
__device__ __forceinline__ uint32_t smem_u32(const void* p) {
    uint32_t a;
    asm("{ .reg .u64 t; cvta.to.shared.u64 t, %1; cvt.u32.u64 %0, t; }"
        : "=r"(a) : "l"(p));
    return a;
}
__device__ __forceinline__ void cpa16(uint32_t dst, const void* src) {
    asm volatile("cp.async.cg.shared.global [%0], [%1], 16;"
                 :: "r"(dst), "l"(src));
}
__device__ __forceinline__ void ldsm4(uint32_t addr, uint32_t* r) {
    asm volatile("ldmatrix.sync.aligned.m8n8.x4.shared.b16 {%0,%1,%2,%3}, [%4];"
                 : "=r"(r[0]), "=r"(r[1]), "=r"(r[2]), "=r"(r[3]) : "r"(addr));
}
__device__ __forceinline__ void ldsm4t(uint32_t addr, uint32_t* r) {
    asm volatile("ldmatrix.sync.aligned.m8n8.x4.trans.shared.b16 {%0,%1,%2,%3}, [%4];"
                 : "=r"(r[0]), "=r"(r[1]), "=r"(r[2]), "=r"(r[3]) : "r"(addr));
}
__device__ __forceinline__ void mma16816(float* c, const uint32_t* a,
                                         uint32_t b0, uint32_t b1) {
    asm volatile(
        "mma.sync.aligned.m16n8k16.row.col.f32.f16.f16.f32 "
        "{%0,%1,%2,%3}, {%4,%5,%6,%7}, {%8,%9}, {%0,%1,%2,%3};"
        : "+f"(c[0]), "+f"(c[1]), "+f"(c[2]), "+f"(c[3])
        : "r"(a[0]), "r"(a[1]), "r"(a[2]), "r"(a[3]), "r"(b0), "r"(b1));
}
__device__ __forceinline__ void split2(float x0, float x1,
                                       uint32_t& hi, uint32_t& lo) {
    __half h0 = __float2half_rn(x0), h1 = __float2half_rn(x1);
    __half l0 = __float2half_rn(x0 - __half2float(h0));
    __half l1 = __float2half_rn(x1 - __half2float(h1));
    __half2 hp = __halves2half2(h0, h1), lp = __halves2half2(l0, l1);
    hi = *reinterpret_cast<uint32_t*>(&hp);
    lo = *reinterpret_cast<uint32_t*>(&lp);
}
// byte offset in an f16 tile (256B rows), 16B-chunk XOR swizzle
__device__ __forceinline__ uint32_t swz(int row, int col) {
    return (uint32_t)(row * 256) + (uint32_t)((((col >> 3) ^ (row & 7)) & 15) << 4)
         + (uint32_t)((col & 7) << 1);
}
__device__ __forceinline__ uint32_t swz16(int row, int ch) {
    return (uint32_t)(row * 256) + (uint32_t)(((ch ^ (row & 7)) & 15) << 4);
}

// smem layout: P tiles 48 rows; K hi/lo tiles 96 rows; V (hi-only) over K-hi
#define SM_PHI  0
#define SM_PLO  12288
#define SM_KVHI 24576
#define SM_KLO  49152
#define SM_IDX  73728    /* 96 ints */
#define SM_RED  74240    /* redm[2][48], redl[2][48] */
#define SMEM_TOTAL 75008

// Dead-code-in-practice fallback for nc > 96 (slow, simple, correct).
__device__ __noinline__ void attn_fallback(int b, int c, int k, int nc,
                                           const int* idxs,
                                           const float* query,
                                           const float* value,
                                           float* out) {
    for (int r = threadIdx.x; r < nc; r += blockDim.x) {
        int i = idxs[r];
        const float* q = query + (((size_t)b * L_ + i) * V_ + k) * D_;
        float m = -1e30f;
        for (int jj = 0; jj < nc; jj++) {
            const float* kr = g_sumK + ((size_t)b * L_ + idxs[jj]) * D_;
            float s = 0.f;
            for (int d = 0; d < D_; d++) s += q[d] * kr[d];
            m = fmaxf(m, s * SCALE_);
        }
        float l = 0.f;
        for (int jj = 0; jj < nc; jj++) {
            const float* kr = g_sumK + ((size_t)b * L_ + idxs[jj]) * D_;
            float s = 0.f;
            for (int d = 0; d < D_; d++) s += q[d] * kr[d];
            l += __expf(s * SCALE_ - m);
        }
        for (int d0 = 0; d0 < D_; d0 += 32) {
            float acc[32];
            for (int e = 0; e < 32; e++) acc[e] = 0.f;
            for (int jj = 0; jj < nc; jj++) {
                const float* kr = g_sumK + ((size_t)b * L_ + idxs[jj]) * D_;
                float s = 0.f;
                for (int d = 0; d < D_; d++) s += q[d] * kr[d];
                float p = __expf(s * SCALE_ - m) / l;
                const float* vr = value +
                    (((size_t)b * L_ + idxs[jj]) * V_ + k) * D_ + d0;
                for (int e = 0; e < 32; e++) acc[e] += p * vr[e];
            }
            float* dst = out + (((size_t)b * L_ + i) * V_ + k) * D_ + d0;
            for (int e = 0; e < 32; e++) dst[e] = acc[e];
        }
    }
}

// ===========================================================================
// HMMA clustered attention (R12 structure + strength-reduced addresses).
// CTA = (head, cluster-rank, z-half of 48 rows). 192 thr, 3 CTAs/SM.
// ===========================================================================
extern __shared__ char smx[];

__global__ void __launch_bounds__(192, 3)
attn_mma_kernel(const float* __restrict__ query,
                const float* __restrict__ value,
                float* __restrict__ out) {
    const int k = blockIdx.x, cl = blockIdx.y, z = blockIdx.z;
    const int tid = threadIdx.x;
    const int lane = tid & 31;
    const int w = tid >> 5;          // 0..5
    const int half = w & 1;
    const int sid = w >> 1;          // strip 0..2

    // ---- LPT: every warp ranks clusters by descending count (no smem/bar)
    int ordv;
    {
        int key = (lane < 16)
                ? ((g_cnt[lane >> 3][lane & 7] << 4) | (15 - lane)) : -1;
        int rank = 0;
#pragma unroll
        for (int j = 0; j < 16; j++) {
            int other = __shfl_sync(0xffffffffu, key, j);
            if (other > key) rank++;
        }
        unsigned m = __ballot_sync(0xffffffffu, lane < 16 && rank == cl);
        ordv = __ffs(m) - 1;
    }
    const int b = ordv >> 3, c = ordv & 7;
    const int* __restrict__ gidx = g_idx[b][c];

    const int nc = g_cnt[b][c];
    if (nc == 0) return;
    if (nc > NR_MAX) {
        if (z == 0) attn_fallback(b, c, k, nc, gidx, query, value, out);
        return;
    }
    const int rowbase = z * 48;
    int nloc = nc - rowbase;
    if (nloc <= 0) return;
    if (nloc > 48) nloc = 48;

    const int nr = (nc + 15) & ~15;           // K/V rows, <= 96
    const int npair = nr >> 4;                // <= 6

    const uint32_t sb  = smem_u32(smx);
    const uint32_t phi = sb + SM_PHI, plo = sb + SM_PLO;
    const uint32_t kvh = sb + SM_KVHI, klo = sb + SM_KLO;
    int* idxs = (int*)(smx + SM_IDX);

    // ---- idx -> smem (visible after the fill barrier; fills use g_idx) ---
    for (int t = tid; t < nc; t += 192) idxs[t] = gidx[t];

    // ---- K (pre-split hi/lo) via cp.async, addresses from g_idx ----------
    for (int t = tid; t < nr * 16; t += 192) {
        int row = t >> 4, ch = t & 15;
        uint32_t so = swz16(row, ch);
        if (row < nc) {
            size_t kb = (((size_t)b * L_ + gidx[row]) << 8) + (ch << 4);
            cpa16(kvh + so, (const char*)g_sKh + kb);
            cpa16(klo + so, (const char*)g_sKl + kb);
        } else {
            uint4 zz = make_uint4(0, 0, 0, 0);
            *(uint4*)(smx + SM_KVHI + so) = zz;
            *(uint4*)(smx + SM_KLO + so) = zz;
        }
    }
    asm volatile("cp.async.commit_group;");

    // ---- Q: direct LDG.128 (one row per warp-inst) -> split -> STS.64 ----
    {
        float4 qv[8];
#pragma unroll
        for (int i = 0; i < 8; i++) {
            int gr = rowbase + w + 6 * i;
            if (gr < nc)
                qv[i] = ((const float4*)query)[
                    ((((size_t)b * L_ + gidx[gr]) * V_ + k) << 5) + lane];
        }
#pragma unroll
        for (int i = 0; i < 8; i++) {
            int lr = w + 6 * i;
            int gr = rowbase + lr;
            uint32_t h0 = 0, l0 = 0, h1 = 0, l1 = 0;
            if (gr < nc) {
                split2(qv[i].x * SCALE_, qv[i].y * SCALE_, h0, l0);
                split2(qv[i].z * SCALE_, qv[i].w * SCALE_, h1, l1);
            }
            uint32_t off = swz(lr, lane * 4);   // cols 4L..4L+3 share a chunk
            *(uint2*)(smx + SM_PHI + off) = make_uint2(h0, h1);
            *(uint2*)(smx + SM_PLO + off) = make_uint2(l0, l1);
        }
    }
    asm volatile("cp.async.wait_group 0;" ::: "memory");
    __syncthreads();   // [bar 1] fills + idxs visible

    float* redm = (float*)(smx + SM_RED);     // [2][48]
    float* redl = redm + 96;

    const int g  = lane >> 3;
    const int l7 = lane & 7;
    const int rA = l7 + ((g & 1) << 3);
    const int cA8 = (g >> 1) & 1;             // cA>>3
    const int rB = l7 + (((g >> 1) & 1) << 3);
    const int cB8 = g & 1;                    // cB>>3
    const int colb = (lane & 3) << 1;
    const int qr = lane >> 2;

    const int lr0 = sid * 16;
    const bool active = lr0 < nloc;
    const int r1 = lr0 + qr, r2 = r1 + 8;     // local P rows

    // Strength-reduced ldsm bases: swz(row, col) with col&7==0 and
    // row&7 == l7 factors as rowbase*256 + ((2s ^ l7 ^ c8)<<4).
    const uint32_t aBaseHi = phi + (uint32_t)(lr0 + rA) * 256;   // + chunkA
    const uint32_t aBaseLo = plo + (uint32_t)(lr0 + rA) * 256;
    const uint32_t bBaseHi = kvh + (uint32_t)rB * 256;           // + ti*4096 + chunkB
    const uint32_t bBaseLo = klo + (uint32_t)rB * 256;
    const uint32_t CA = (uint32_t)(l7 ^ cA8);
    const uint32_t CB = (uint32_t)(l7 ^ cB8);

    // ================= S = Q * Ksum^T (full 3-term) ====================
    float cS[6][4];
#pragma unroll
    for (int n = 0; n < 6; n++)
#pragma unroll
        for (int r = 0; r < 4; r++) cS[n][r] = 0.f;

    if (active) {
#pragma unroll
        for (int s = 0; s < 8; s++) {
            const uint32_t t2 = (uint32_t)(2 * s);
            const uint32_t chA = ((t2 ^ CA) << 4);
            const uint32_t chB = ((t2 ^ CB) << 4);
            uint32_t ah[4], al[4], bh[3][4], bl[3][4];
            ldsm4(aBaseHi + chA, ah);
            ldsm4(aBaseLo + chA, al);
#pragma unroll
            for (int u = 0; u < 3; u++) {
                int ti = half + 2 * u;
                if (ti < npair) {
                    ldsm4(bBaseHi + (uint32_t)ti * 4096 + chB, bh[u]);
                    ldsm4(bBaseLo + (uint32_t)ti * 4096 + chB, bl[u]);
                }
            }
#pragma unroll
            for (int u = 0; u < 3; u++)
                if (half + 2 * u < npair) {
                    mma16816(cS[2 * u],     ah, bh[u][0], bh[u][1]);
                    mma16816(cS[2 * u + 1], ah, bh[u][2], bh[u][3]);
                }
#pragma unroll
            for (int u = 0; u < 3; u++)
                if (half + 2 * u < npair) {
                    mma16816(cS[2 * u],     ah, bl[u][0], bl[u][1]);
                    mma16816(cS[2 * u + 1], ah, bl[u][2], bl[u][3]);
                }
#pragma unroll
            for (int u = 0; u < 3; u++)
                if (half + 2 * u < npair) {
                    mma16816(cS[2 * u],     al, bh[u][0], bh[u][1]);
                    mma16816(cS[2 * u + 1], al, bh[u][2], bh[u][3]);
                }
        }

        float m0 = -1e30f, m1 = -1e30f;
#pragma unroll
        for (int u = 0; u < 3; u++) {
            int ti = half + 2 * u;
            if (ti < npair) {
#pragma unroll
                for (int sub = 0; sub < 2; sub++) {
                    int n = 2 * u + sub;
                    int c0 = ti * 16 + sub * 8 + colb;
                    if (c0 < nc)     { m0 = fmaxf(m0, cS[n][0]); m1 = fmaxf(m1, cS[n][2]); }
                    if (c0 + 1 < nc) { m0 = fmaxf(m0, cS[n][1]); m1 = fmaxf(m1, cS[n][3]); }
                }
            }
        }
        m0 = fmaxf(m0, __shfl_xor_sync(0xffffffffu, m0, 1));
        m0 = fmaxf(m0, __shfl_xor_sync(0xffffffffu, m0, 2));
        m1 = fmaxf(m1, __shfl_xor_sync(0xffffffffu, m1, 1));
        m1 = fmaxf(m1, __shfl_xor_sync(0xffffffffu, m1, 2));
        if ((lane & 3) == 0) {
            redm[half * 48 + r1] = m0;
            redm[half * 48 + r2] = m1;
        }
    }
    __syncthreads();   // [bar 2] K ldsm done (K tiles dead) + partial maxes

    // ---- V batch A: direct LDG of rows [0,48) (latency hidden by softmax)
    float4 va[8];
#pragma unroll
    for (int i = 0; i < 8; i++) {
        int row = w + 6 * i;              // 0..47
        if (row < nc)
            va[i] = ((const float4*)value)[
                ((((size_t)b * L_ + idxs[row]) * V_ + k) << 5) + lane];
    }

    // ---- softmax: exp, P (hi only) -> smem, partial l --------------------
    if (active) {
        float mt0 = fmaxf(redm[r1], redm[48 + r1]);
        float mt1 = fmaxf(redm[r2], redm[48 + r2]);
        float l0 = 0.f, l1 = 0.f;
#pragma unroll
        for (int u = 0; u < 3; u++) {
            int ti = half + 2 * u;
            if (ti < npair) {
#pragma unroll
                for (int sub = 0; sub < 2; sub++) {
                    int n = 2 * u + sub;
                    int c0 = ti * 16 + sub * 8 + colb;
                    float p0 = (c0     < nc) ? __expf(cS[n][0] - mt0) : 0.f;
                    float p1 = (c0 + 1 < nc) ? __expf(cS[n][1] - mt0) : 0.f;
                    float p2 = (c0     < nc) ? __expf(cS[n][2] - mt1) : 0.f;
                    float p3 = (c0 + 1 < nc) ? __expf(cS[n][3] - mt1) : 0.f;
                    l0 += p0 + p1; l1 += p2 + p3;
                    *(uint32_t*)(smx + SM_PHI + swz(r1, c0)) = packh2(p0, p1);
                    *(uint32_t*)(smx + SM_PHI + swz(r2, c0)) = packh2(p2, p3);
                }
            }
        }
        l0 += __shfl_xor_sync(0xffffffffu, l0, 1);
        l0 += __shfl_xor_sync(0xffffffffu, l0, 2);
        l1 += __shfl_xor_sync(0xffffffffu, l1, 1);
        l1 += __shfl_xor_sync(0xffffffffu, l1, 2);
        if ((lane & 3) == 0) {
            redl[half * 48 + r1] = l0;
            redl[half * 48 + r2] = l1;
        }
    }

    // ---- V batch B LDG (rows [48,96)), then store both batches as fp16 hi
    {
        float4 vbB[8];
#pragma unroll
        for (int i = 0; i < 8; i++) {
            int row = 48 + w + 6 * i;     // 48..95
            if (row < nc)
                vbB[i] = ((const float4*)value)[
                    ((((size_t)b * L_ + idxs[row]) * V_ + k) << 5) + lane];
        }
#pragma unroll
        for (int i = 0; i < 8; i++) {
            int row = w + 6 * i;
            uint32_t h0 = 0, h1 = 0;
            if (row < nc) {
                h0 = packh2(va[i].x, va[i].y);
                h1 = packh2(va[i].z, va[i].w);
            }
            if (row < nr)
                *(uint2*)(smx + SM_KVHI + swz(row, lane * 4)) = make_uint2(h0, h1);
        }
#pragma unroll
        for (int i = 0; i < 8; i++) {
            int row = 48 + w + 6 * i;
            uint32_t h0 = 0, h1 = 0;
            if (row < nc) {
                h0 = packh2(vbB[i].x, vbB[i].y);
                h1 = packh2(vbB[i].z, vbB[i].w);
            }
            if (row < nr)
                *(uint2*)(smx + SM_KVHI + swz(row, lane * 4)) = make_uint2(h0, h1);
        }
    }
    __syncthreads();   // [bar 3] V tile + P tiles + partial l complete

    // ================= O = Phi * Vhi  (d-range = half*64..+63) =============
    if (active) {
        float o[8][4];
#pragma unroll
        for (int n = 0; n < 8; n++)
#pragma unroll
            for (int r = 0; r < 4; r++) o[n][r] = 0.f;

        // strength-reduced PV bases: P row lr0+rA; V rows kt*16+rA
        const uint32_t pBase = phi + (uint32_t)(lr0 + rA) * 256;
        const uint32_t vBase = kvh + (uint32_t)rA * 256;
#pragma unroll
        for (int kt = 0; kt < 6; kt++) {
            if (kt < npair) {
                const uint32_t chP = (((uint32_t)(2 * kt) ^ CA) << 4);
                uint32_t ph[4], vh[4][4];
                ldsm4(pBase + chP, ph);
#pragma unroll
                for (int dq = 0; dq < 4; dq++) {
                    int dp = half * 4 + dq;
                    const uint32_t chV = (((uint32_t)(2 * dp) ^ CA) << 4);
                    ldsm4t(vBase + (uint32_t)kt * 4096 + chV, vh[dq]);
                }
#pragma unroll
                for (int dq = 0; dq < 4; dq++) {
                    mma16816(o[2 * dq],     ph, vh[dq][0], vh[dq][1]);
                    mma16816(o[2 * dq + 1], ph, vh[dq][2], vh[dq][3]);
                }
            }
        }

        // ---- epilogue (streaming stores; out is write-once)
        float lt0 = redl[r1] + redl[48 + r1];
        float lt1 = redl[r2] + redl[48 + r2];
        float i0 = 1.f / lt0, i1 = 1.f / lt1;
        int gr1 = rowbase + r1, gr2 = rowbase + r2;
        float* d1 = (gr1 < nc)
            ? out + (((size_t)b * L_ + idxs[gr1]) * V_ + k) * D_ : nullptr;
        float* d2 = (gr2 < nc)
            ? out + (((size_t)b * L_ + idxs[gr2]) * V_ + k) * D_ : nullptr;
#pragma unroll
        for (int n = 0; n < 8; n++) {
            int col = half * 64 + (n >> 1) * 16 + (n & 1) * 8 + colb;
            if (d1) __stcs((float2*)(d1 + col),
                           make_float2(o[n][0] * i0, o[n][1] * i0));
            if (d2) __stcs((float2*)(d2 + col),
                           make_float2(o[n][2] * i1, o[n][3] * i1));
        }
    }
}

extern "C" void kernel_launch(void* const* d_in, const int* in_sizes, int n_in,
                              void* d_out, int out_size) {
    (void)in_sizes; (void)n_in; (void)out_size;
    const float* query = (const float*)d_in[0];
    const float* key   = (const float*)d_in[1];
    const float* value = (const float*)d_in[2];
    const int*   label = (const int*)d_in[3];
    float* out = (float*)d_out;

    prep_kernel<<<1040, 512>>>((const float4*)key, label);
    cudaFuncSetAttribute(attn_mma_kernel,
                         cudaFuncAttributeMaxDynamicSharedMemorySize, SMEM_TOTAL);
    attn_mma_kernel<<<dim3(V_, 16, 2), 192, SMEM_TOTAL>>>(query, value, out);
}